// round 16
// baseline (speedup 1.0000x reference)
#include <cuda_runtime.h>
#include <cuda_fp16.h>
#include <math.h>

#define N_NODES 100000
#define N_EDGES 3200000
#define IN_CH   256
#define HID     16
#define OUT_CH  40
#define CAP     96      // max in-degree capacity (Poisson(32): P(>=96) ~ 1e-18)

// ---- scratch (static device globals; referenced ONLY inside kernels) ----
__device__ int    g_cnt   [N_NODES];
__device__ int    g_bucket[(size_t)N_NODES * CAP];
__device__ float  g_dinv  [N_NODES];
__device__ __align__(16) __half g_t1s16[N_NODES * 16]; // (x@W1)*dinv, fp16
__device__ __align__(16) __half g_hs16 [N_NODES * 16]; // relu(l1)*dinv, fp16
__device__ __align__(16) float2 g_g2   [N_NODES * 8];  // layer-2 pre-GEMM, fp32

// ---------------------------------------------------------------
// bucket build with inline dtype detect
__global__ void k_build(const void* __restrict__ ei) {
    const int* e32 = (const int*)ei;
    int z = 0;
#pragma unroll
    for (int j = 0; j < 8; j++) z |= __ldg(&e32[2 * j + 1]);
    bool is64 = (z == 0);

    int i4 = blockIdx.x * blockDim.x + threadIdx.x;
    if (i4 * 4 >= N_EDGES) return;
    int r[4], c[4];
    if (!is64) {
        const int* e = (const int*)ei;
        int4 rv = __ldg((const int4*)e + i4);
        int4 cv = __ldg((const int4*)(e + N_EDGES) + i4);
        r[0] = rv.x; r[1] = rv.y; r[2] = rv.z; r[3] = rv.w;
        c[0] = cv.x; c[1] = cv.y; c[2] = cv.z; c[3] = cv.w;
    } else {
        const long long* e = (const long long*)ei;
        longlong2 a0 = __ldg((const longlong2*)e + i4 * 2);
        longlong2 a1 = __ldg((const longlong2*)e + i4 * 2 + 1);
        longlong2 b0 = __ldg((const longlong2*)(e + N_EDGES) + i4 * 2);
        longlong2 b1 = __ldg((const longlong2*)(e + N_EDGES) + i4 * 2 + 1);
        r[0] = (int)a0.x; r[1] = (int)a0.y; r[2] = (int)a1.x; r[3] = (int)a1.y;
        c[0] = (int)b0.x; c[1] = (int)b0.y; c[2] = (int)b1.x; c[3] = (int)b1.y;
    }
#pragma unroll
    for (int k = 0; k < 4; k++) {
        int pos = atomicAdd(&g_cnt[c[k]], 1);
        if (pos < CAP) g_bucket[(size_t)c[k] * CAP + pos] = r[k];
    }
}

// ---------------------------------------------------------------
// t1s16 = fp16((x @ W1) * dinv); stores dinv. Register-tiled, f32x2 FMA.
__global__ void __launch_bounds__(256) k_gemm1(const float* __restrict__ x,
                                               const float* __restrict__ W1) {
    __shared__ float  xs[32][257];
    __shared__ float4 wsm[256 * 4];
    int t = threadIdx.x;
    int node0 = blockIdx.x * 256;

    const float4* W14 = (const float4*)W1;
#pragma unroll
    for (int j = 0; j < 4; j++) wsm[t + 256 * j] = W14[t + 256 * j];

    unsigned long long acc2[8];
#pragma unroll
    for (int h = 0; h < 8; h++) acc2[h] = 0ULL;

    int f4 = t & 7;
    int nl = t >> 3;

#pragma unroll 1
    for (int kc = 0; kc < 256; kc += 32) {
        __syncthreads();
#pragma unroll
        for (int rep = 0; rep < 8; rep++) {
            int n = nl + 32 * rep;
            int node = node0 + n;
            float4 v = (node < N_NODES)
                ? __ldg((const float4*)(x + (size_t)node * 256 + kc) + f4)
                : make_float4(0.f, 0.f, 0.f, 0.f);
            xs[f4 * 4 + 0][n] = v.x;
            xs[f4 * 4 + 1][n] = v.y;
            xs[f4 * 4 + 2][n] = v.z;
            xs[f4 * 4 + 3][n] = v.w;
        }
        __syncthreads();
#pragma unroll
        for (int k = 0; k < 32; k++) {
            float xr = xs[k][t];
            unsigned long long xr2;
            asm("mov.b64 %0, {%1, %1};" : "=l"(xr2) : "f"(xr));
            const double2* wd = (const double2*)(wsm + (kc + k) * 4);
            double2 wa = wd[0], wb = wd[1], wc = wd[2], we = wd[3];
            asm("fma.rn.f32x2 %0, %1, %2, %0;" : "+l"(acc2[0]) : "l"(xr2), "l"(__double_as_longlong(wa.x)));
            asm("fma.rn.f32x2 %0, %1, %2, %0;" : "+l"(acc2[1]) : "l"(xr2), "l"(__double_as_longlong(wa.y)));
            asm("fma.rn.f32x2 %0, %1, %2, %0;" : "+l"(acc2[2]) : "l"(xr2), "l"(__double_as_longlong(wb.x)));
            asm("fma.rn.f32x2 %0, %1, %2, %0;" : "+l"(acc2[3]) : "l"(xr2), "l"(__double_as_longlong(wb.y)));
            asm("fma.rn.f32x2 %0, %1, %2, %0;" : "+l"(acc2[4]) : "l"(xr2), "l"(__double_as_longlong(wc.x)));
            asm("fma.rn.f32x2 %0, %1, %2, %0;" : "+l"(acc2[5]) : "l"(xr2), "l"(__double_as_longlong(wc.y)));
            asm("fma.rn.f32x2 %0, %1, %2, %0;" : "+l"(acc2[6]) : "l"(xr2), "l"(__double_as_longlong(we.x)));
            asm("fma.rn.f32x2 %0, %1, %2, %0;" : "+l"(acc2[7]) : "l"(xr2), "l"(__double_as_longlong(we.y)));
        }
    }

    int node = node0 + t;
    if (node < N_NODES) {
        float d = rsqrtf(1.0f + (float)g_cnt[node]);
        g_dinv[node] = d;
        __half2 h2[8];
#pragma unroll
        for (int j = 0; j < 8; j++) {
            float lo, hi;
            asm("mov.b64 {%0, %1}, %2;" : "=f"(lo), "=f"(hi) : "l"(acc2[j]));
            h2[j] = __floats2half2_rn(lo * d, hi * d);
        }
        uint4* dst = (uint4*)(g_t1s16 + (size_t)node * 16);
        dst[0] = *(uint4*)&h2[0];
        dst[1] = *(uint4*)&h2[4];
    }
}

// ---------------------------------------------------------------
// layer-1 pull-aggregate: ONE WARP PER NODE, shuffle-distributed indices.
// lane = slot(0..15)*2 + half(0..1): 16 neighbors gathered per step.
__global__ void __launch_bounds__(256) k_agg0(const float* __restrict__ b1) {
    int warp = (blockIdx.x * blockDim.x + threadIdx.x) >> 5;
    int lane = threadIdx.x & 31;
    if (warp >= N_NODES) return;
    int node = warp;
    int slot = lane >> 1;     // 0..15
    int half = lane & 1;

    int cnt = g_cnt[node]; if (cnt > CAP) cnt = CAP;
    const int* bk = g_bucket + (size_t)node * CAP;
    const uint4* __restrict__ src = (const uint4*)g_t1s16;

    // preload all indices coalesced into registers (garbage beyond cnt unused)
    int idx0 = __ldg(bk + lane);
    int idx1 = __ldg(bk + 32 + lane);
    int idx2 = __ldg(bk + 64 + lane);

    float acc[8];
#pragma unroll
    for (int i = 0; i < 8; i++) acc[i] = 0.f;

#define ADDV(u) do { \
        __half2* _p = (__half2*)&(u); \
        float2 _f0 = __half22float2(_p[0]); \
        float2 _f1 = __half22float2(_p[1]); \
        float2 _f2 = __half22float2(_p[2]); \
        float2 _f3 = __half22float2(_p[3]); \
        acc[0] += _f0.x; acc[1] += _f0.y; acc[2] += _f1.x; acc[3] += _f1.y; \
        acc[4] += _f2.x; acc[5] += _f2.y; acc[6] += _f3.x; acc[7] += _f3.y; \
    } while (0)

#define SEG0(IDX, BASE) do { \
        _Pragma("unroll") \
        for (int k = 0; k < 2; k++) { \
            int j = (BASE) + k * 16 + slot; \
            int r = __shfl_sync(0xffffffffu, (IDX), j - (BASE)); \
            if (j < cnt) { uint4 v = __ldg(&src[r * 2 + half]); ADDV(v); } \
        } \
    } while (0)

    { uint4 v = src[node * 2 + half]; if (slot == 0) ADDV(v); }  // self term
    SEG0(idx0, 0);
    if (cnt > 32) SEG0(idx1, 32);
    if (cnt > 64) SEG0(idx2, 64);
#undef SEG0
#undef ADDV

    // reduce over slots (lane bits 1..4), keep half (bit 0)
#pragma unroll
    for (int i = 0; i < 8; i++) {
        acc[i] += __shfl_xor_sync(0xffffffffu, acc[i], 2);
        acc[i] += __shfl_xor_sync(0xffffffffu, acc[i], 4);
        acc[i] += __shfl_xor_sync(0xffffffffu, acc[i], 8);
        acc[i] += __shfl_xor_sync(0xffffffffu, acc[i], 16);
    }

    if (slot == 0) {
        float d = g_dinv[node];
        __half2 h2[4];
#pragma unroll
        for (int p = 0; p < 4; p++) {
            float a = fmaxf(fmaf(acc[2 * p + 0], d, __ldg(&b1[half * 8 + 2 * p + 0])), 0.f) * d;
            float b = fmaxf(fmaf(acc[2 * p + 1], d, __ldg(&b1[half * 8 + 2 * p + 1])), 0.f) * d;
            h2[p] = __floats2half2_rn(a, b);
        }
        ((uint4*)(g_hs16 + (size_t)node * 16))[half] = *(uint4*)&h2[0];
    }
}

// ---------------------------------------------------------------
// layer-2 pull-aggregate: warp per node, shuffle-distributed indices.
// lane = slot(0..3)*8 + c2(0..7); 8 independent gathers per lane per segment.
__global__ void __launch_bounds__(256) k_agg1() {
    int warp = (blockIdx.x * blockDim.x + threadIdx.x) >> 5;
    int lane = threadIdx.x & 31;
    if (warp >= N_NODES) return;
    int node = warp;
    int slot = lane >> 3;
    int c2   = lane & 7;

    int cnt = g_cnt[node]; if (cnt > CAP) cnt = CAP;
    const int* bk = g_bucket + (size_t)node * CAP;
    const __half2* __restrict__ hs2 = (const __half2*)g_hs16;

    int idx0 = __ldg(bk + lane);
    int idx1 = __ldg(bk + 32 + lane);
    int idx2 = __ldg(bk + 64 + lane);

    float2 acc = make_float2(0.f, 0.f);
    if (slot == 0) {
        float2 v = __half22float2(__ldg(&hs2[node * 8 + c2]));
        acc.x = v.x; acc.y = v.y;
    }

#define SEG1(IDX, BASE) do { \
        _Pragma("unroll") \
        for (int k = 0; k < 8; k++) { \
            int j = (BASE) + k * 4 + slot; \
            int r = __shfl_sync(0xffffffffu, (IDX), j - (BASE)); \
            if (j < cnt) { \
                float2 v = __half22float2(__ldg(&hs2[r * 8 + c2])); \
                acc.x += v.x; acc.y += v.y; \
            } \
        } \
    } while (0)

    SEG1(idx0, 0);
    if (cnt > 32) SEG1(idx1, 32);
    if (cnt > 64) SEG1(idx2, 64);
#undef SEG1

    acc.x += __shfl_xor_sync(0xffffffffu, acc.x, 8);
    acc.y += __shfl_xor_sync(0xffffffffu, acc.y, 8);
    acc.x += __shfl_xor_sync(0xffffffffu, acc.x, 16);
    acc.y += __shfl_xor_sync(0xffffffffu, acc.y, 16);

    if (lane < 8) {
        float d = g_dinv[node];
        g_g2[node * 8 + lane] = make_float2(acc.x * d, acc.y * d);
    }
}

// dense final GEMM + log_softmax: 1 thread = 1 node, W2/b2 in smem.
__global__ void __launch_bounds__(256) k_gemm2(const float* __restrict__ W2,
                                               const float* __restrict__ b2,
                                               float* __restrict__ out) {
    __shared__ float w2s[16 * 40];
    __shared__ float b2s[OUT_CH];
    int t = threadIdx.x;
    for (int i = t; i < 16 * 40; i += 256) w2s[i] = __ldg(&W2[i]);
    if (t < OUT_CH) b2s[t] = __ldg(&b2[t]);
    __syncthreads();

    int node = blockIdx.x * 256 + t;
    if (node >= N_NODES) return;

    float g[16];
    const float4* gp = (const float4*)(g_g2 + (size_t)node * 8);
    float4 v0 = gp[0], v1 = gp[1], v2 = gp[2], v3 = gp[3];
    g[0] = v0.x; g[1] = v0.y; g[2] = v0.z;  g[3] = v0.w;
    g[4] = v1.x; g[5] = v1.y; g[6] = v1.z;  g[7] = v1.w;
    g[8] = v2.x; g[9] = v2.y; g[10] = v2.z; g[11] = v2.w;
    g[12] = v3.x; g[13] = v3.y; g[14] = v3.z; g[15] = v3.w;

    float lg[40];
#pragma unroll
    for (int o = 0; o < 40; o++) lg[o] = b2s[o];
#pragma unroll
    for (int k = 0; k < 16; k++) {
        float gk = g[k];
#pragma unroll
        for (int o4 = 0; o4 < 10; o4++) {
            float4 w = *(const float4*)&w2s[k * 40 + o4 * 4];
            lg[o4 * 4 + 0] = fmaf(gk, w.x, lg[o4 * 4 + 0]);
            lg[o4 * 4 + 1] = fmaf(gk, w.y, lg[o4 * 4 + 1]);
            lg[o4 * 4 + 2] = fmaf(gk, w.z, lg[o4 * 4 + 2]);
            lg[o4 * 4 + 3] = fmaf(gk, w.w, lg[o4 * 4 + 3]);
        }
    }

    float m = lg[0];
#pragma unroll
    for (int o = 1; o < 40; o++) m = fmaxf(m, lg[o]);
    float s = 0.f;
#pragma unroll
    for (int o = 0; o < 40; o++) s += __expf(lg[o] - m);
    float lse = m + __logf(s);

    float4* op = (float4*)(out + (size_t)node * 40);
#pragma unroll
    for (int o4 = 0; o4 < 10; o4++)
        op[o4] = make_float4(lg[o4 * 4 + 0] - lse, lg[o4 * 4 + 1] - lse,
                             lg[o4 * 4 + 2] - lse, lg[o4 * 4 + 3] - lse);
}

// ---------------------------------------------------------------
extern "C" void kernel_launch(void* const* d_in, const int* in_sizes, int n_in,
                              void* d_out, int out_size) {
    const float* x  = (const float*)d_in[0];
    const void*  ei = d_in[1];
    const float* W1 = (const float*)d_in[2];
    const float* b1 = (const float*)d_in[3];
    const float* W2 = (const float*)d_in[4];
    const float* b2 = (const float*)d_in[5];
    float* out = (float*)d_out;

    static void* cntp = nullptr;
    if (!cntp) cudaGetSymbolAddress(&cntp, g_cnt);

    cudaMemsetAsync(cntp, 0, N_NODES * sizeof(int), 0);
    k_build <<<(N_EDGES / 4 + 255) / 256, 256>>>(ei);
    k_gemm1 <<<(N_NODES + 255) / 256, 256>>>(x, W1);
    k_agg0  <<<(N_NODES * 32 + 255) / 256, 256>>>(b1);
    k_agg1  <<<(N_NODES * 32 + 255) / 256, 256>>>();
    k_gemm2 <<<(N_NODES + 255) / 256, 256>>>(W2, b2, out);
}

// round 17
// speedup vs baseline: 1.0646x; 1.0646x over previous
#include <cuda_runtime.h>
#include <cuda_fp16.h>
#include <math.h>

#define N_NODES 100000
#define N_EDGES 3200000
#define IN_CH   256
#define HID     16
#define OUT_CH  40
#define CAP     96      // max in-degree capacity (Poisson(32): P(>=96) ~ 1e-18)

// ---- scratch (static device globals; referenced ONLY inside kernels) ----
__device__ int    g_cnt   [N_NODES];
__device__ int    g_bucket[(size_t)N_NODES * CAP];
__device__ float  g_dinv  [N_NODES];
__device__ __align__(16) __half g_t1s16[N_NODES * 16]; // (x@W1)*dinv, fp16
__device__ __align__(16) __half g_hs16 [N_NODES * 16]; // relu(l1)*dinv, fp16
__device__ __align__(16) float2 g_g2   [N_NODES * 8];  // layer-2 pre-GEMM, fp32

// ---------------------------------------------------------------
// bucket build with inline dtype detect
__global__ void k_build(const void* __restrict__ ei) {
    const int* e32 = (const int*)ei;
    int z = 0;
#pragma unroll
    for (int j = 0; j < 8; j++) z |= __ldg(&e32[2 * j + 1]);
    bool is64 = (z == 0);

    int i4 = blockIdx.x * blockDim.x + threadIdx.x;
    if (i4 * 4 >= N_EDGES) return;
    int r[4], c[4];
    if (!is64) {
        const int* e = (const int*)ei;
        int4 rv = __ldg((const int4*)e + i4);
        int4 cv = __ldg((const int4*)(e + N_EDGES) + i4);
        r[0] = rv.x; r[1] = rv.y; r[2] = rv.z; r[3] = rv.w;
        c[0] = cv.x; c[1] = cv.y; c[2] = cv.z; c[3] = cv.w;
    } else {
        const long long* e = (const long long*)ei;
        longlong2 a0 = __ldg((const longlong2*)e + i4 * 2);
        longlong2 a1 = __ldg((const longlong2*)e + i4 * 2 + 1);
        longlong2 b0 = __ldg((const longlong2*)(e + N_EDGES) + i4 * 2);
        longlong2 b1 = __ldg((const longlong2*)(e + N_EDGES) + i4 * 2 + 1);
        r[0] = (int)a0.x; r[1] = (int)a0.y; r[2] = (int)a1.x; r[3] = (int)a1.y;
        c[0] = (int)b0.x; c[1] = (int)b0.y; c[2] = (int)b1.x; c[3] = (int)b1.y;
    }
#pragma unroll
    for (int k = 0; k < 4; k++) {
        int pos = atomicAdd(&g_cnt[c[k]], 1);
        if (pos < CAP) g_bucket[(size_t)c[k] * CAP + pos] = r[k];
    }
}

// ---------------------------------------------------------------
// t1s16 = fp16((x @ W1) * dinv); stores dinv. Register-tiled, f32x2 FMA.
__global__ void __launch_bounds__(256) k_gemm1(const float* __restrict__ x,
                                               const float* __restrict__ W1) {
    __shared__ float  xs[32][257];
    __shared__ float4 wsm[256 * 4];
    int t = threadIdx.x;
    int node0 = blockIdx.x * 256;

    const float4* W14 = (const float4*)W1;
#pragma unroll
    for (int j = 0; j < 4; j++) wsm[t + 256 * j] = W14[t + 256 * j];

    unsigned long long acc2[8];
#pragma unroll
    for (int h = 0; h < 8; h++) acc2[h] = 0ULL;

    int f4 = t & 7;
    int nl = t >> 3;

#pragma unroll 1
    for (int kc = 0; kc < 256; kc += 32) {
        __syncthreads();
#pragma unroll
        for (int rep = 0; rep < 8; rep++) {
            int n = nl + 32 * rep;
            int node = node0 + n;
            float4 v = (node < N_NODES)
                ? __ldg((const float4*)(x + (size_t)node * 256 + kc) + f4)
                : make_float4(0.f, 0.f, 0.f, 0.f);
            xs[f4 * 4 + 0][n] = v.x;
            xs[f4 * 4 + 1][n] = v.y;
            xs[f4 * 4 + 2][n] = v.z;
            xs[f4 * 4 + 3][n] = v.w;
        }
        __syncthreads();
#pragma unroll
        for (int k = 0; k < 32; k++) {
            float xr = xs[k][t];
            unsigned long long xr2;
            asm("mov.b64 %0, {%1, %1};" : "=l"(xr2) : "f"(xr));
            const double2* wd = (const double2*)(wsm + (kc + k) * 4);
            double2 wa = wd[0], wb = wd[1], wc = wd[2], we = wd[3];
            asm("fma.rn.f32x2 %0, %1, %2, %0;" : "+l"(acc2[0]) : "l"(xr2), "l"(__double_as_longlong(wa.x)));
            asm("fma.rn.f32x2 %0, %1, %2, %0;" : "+l"(acc2[1]) : "l"(xr2), "l"(__double_as_longlong(wa.y)));
            asm("fma.rn.f32x2 %0, %1, %2, %0;" : "+l"(acc2[2]) : "l"(xr2), "l"(__double_as_longlong(wb.x)));
            asm("fma.rn.f32x2 %0, %1, %2, %0;" : "+l"(acc2[3]) : "l"(xr2), "l"(__double_as_longlong(wb.y)));
            asm("fma.rn.f32x2 %0, %1, %2, %0;" : "+l"(acc2[4]) : "l"(xr2), "l"(__double_as_longlong(wc.x)));
            asm("fma.rn.f32x2 %0, %1, %2, %0;" : "+l"(acc2[5]) : "l"(xr2), "l"(__double_as_longlong(wc.y)));
            asm("fma.rn.f32x2 %0, %1, %2, %0;" : "+l"(acc2[6]) : "l"(xr2), "l"(__double_as_longlong(we.x)));
            asm("fma.rn.f32x2 %0, %1, %2, %0;" : "+l"(acc2[7]) : "l"(xr2), "l"(__double_as_longlong(we.y)));
        }
    }

    int node = node0 + t;
    if (node < N_NODES) {
        float d = rsqrtf(1.0f + (float)g_cnt[node]);
        g_dinv[node] = d;
        __half2 h2[8];
#pragma unroll
        for (int j = 0; j < 8; j++) {
            float lo, hi;
            asm("mov.b64 {%0, %1}, %2;" : "=f"(lo), "=f"(hi) : "l"(acc2[j]));
            h2[j] = __floats2half2_rn(lo * d, hi * d);
        }
        uint4* dst = (uint4*)(g_t1s16 + (size_t)node * 16);
        dst[0] = *(uint4*)&h2[0];
        dst[1] = *(uint4*)&h2[4];
    }
}

// layer-1 pull-aggregate: 8 lanes/node (slot 0..3 x half 0..1)  [R15 variant]
__global__ void __launch_bounds__(512) k_agg0(const float* __restrict__ b1) {
    int gid = blockIdx.x * blockDim.x + threadIdx.x;
    int node = gid >> 3;
    if (node >= N_NODES) return;
    int sub  = gid & 7;
    int slot = sub >> 1;
    int half = sub & 1;

    int cnt = g_cnt[node]; if (cnt > CAP) cnt = CAP;
    const int* bk = g_bucket + (size_t)node * CAP;
    const uint4* __restrict__ src = (const uint4*)g_t1s16;

    float acc[8];
#pragma unroll
    for (int i = 0; i < 8; i++) acc[i] = 0.f;

#define ADDV(u) do { \
        __half2* _p = (__half2*)&(u); \
        float2 _f0 = __half22float2(_p[0]); \
        float2 _f1 = __half22float2(_p[1]); \
        float2 _f2 = __half22float2(_p[2]); \
        float2 _f3 = __half22float2(_p[3]); \
        acc[0] += _f0.x; acc[1] += _f0.y; acc[2] += _f1.x; acc[3] += _f1.y; \
        acc[4] += _f2.x; acc[5] += _f2.y; acc[6] += _f3.x; acc[7] += _f3.y; \
    } while (0)

    if (slot == 0) { uint4 v = src[node * 2 + half]; ADDV(v); }
    int j = slot;
    for (; j + 4 < cnt; j += 8) {
        int r0 = __ldg(bk + j);
        int r1 = __ldg(bk + j + 4);
        uint4 v0 = __ldg(&src[r0 * 2 + half]);
        uint4 v1 = __ldg(&src[r1 * 2 + half]);
        ADDV(v0); ADDV(v1);
    }
    if (j < cnt) {
        int r = __ldg(bk + j);
        uint4 v = __ldg(&src[r * 2 + half]);
        ADDV(v);
    }
#undef ADDV

#pragma unroll
    for (int i = 0; i < 8; i++) {
        acc[i] += __shfl_xor_sync(0xffffffffu, acc[i], 2);
        acc[i] += __shfl_xor_sync(0xffffffffu, acc[i], 4);
    }

    if (slot == 0) {
        float d = g_dinv[node];
        __half2 h2[4];
#pragma unroll
        for (int p = 0; p < 4; p++) {
            float a = fmaxf(fmaf(acc[2 * p + 0], d, __ldg(&b1[half * 8 + 2 * p + 0])), 0.f) * d;
            float b = fmaxf(fmaf(acc[2 * p + 1], d, __ldg(&b1[half * 8 + 2 * p + 1])), 0.f) * d;
            h2[p] = __floats2half2_rn(a, b);
        }
        ((uint4*)(g_hs16 + (size_t)node * 16))[half] = *(uint4*)&h2[0];
    }
}

// layer-2 pull-aggregate: warp per node, shuffle-distributed indices [R16 variant]
__global__ void __launch_bounds__(256) k_agg1() {
    int warp = (blockIdx.x * blockDim.x + threadIdx.x) >> 5;
    int lane = threadIdx.x & 31;
    if (warp >= N_NODES) return;
    int node = warp;
    int slot = lane >> 3;
    int c2   = lane & 7;

    int cnt = g_cnt[node]; if (cnt > CAP) cnt = CAP;
    const int* bk = g_bucket + (size_t)node * CAP;
    const __half2* __restrict__ hs2 = (const __half2*)g_hs16;

    int idx0 = __ldg(bk + lane);
    int idx1 = __ldg(bk + 32 + lane);
    int idx2 = __ldg(bk + 64 + lane);

    float2 acc = make_float2(0.f, 0.f);
    if (slot == 0) {
        float2 v = __half22float2(__ldg(&hs2[node * 8 + c2]));
        acc.x = v.x; acc.y = v.y;
    }

#define SEG1(IDX, BASE) do { \
        _Pragma("unroll") \
        for (int k = 0; k < 8; k++) { \
            int j = (BASE) + k * 4 + slot; \
            int r = __shfl_sync(0xffffffffu, (IDX), j - (BASE)); \
            if (j < cnt) { \
                float2 v = __half22float2(__ldg(&hs2[r * 8 + c2])); \
                acc.x += v.x; acc.y += v.y; \
            } \
        } \
    } while (0)

    SEG1(idx0, 0);
    if (cnt > 32) SEG1(idx1, 32);
    if (cnt > 64) SEG1(idx2, 64);
#undef SEG1

    acc.x += __shfl_xor_sync(0xffffffffu, acc.x, 8);
    acc.y += __shfl_xor_sync(0xffffffffu, acc.y, 8);
    acc.x += __shfl_xor_sync(0xffffffffu, acc.x, 16);
    acc.y += __shfl_xor_sync(0xffffffffu, acc.y, 16);

    if (lane < 8) {
        float d = g_dinv[node];
        g_g2[node * 8 + lane] = make_float2(acc.x * d, acc.y * d);
    }
}

// dense final GEMM + log_softmax: 1 thread = 1 node, W2/b2 in smem.
__global__ void __launch_bounds__(256) k_gemm2(const float* __restrict__ W2,
                                               const float* __restrict__ b2,
                                               float* __restrict__ out) {
    __shared__ float w2s[16 * 40];
    __shared__ float b2s[OUT_CH];
    int t = threadIdx.x;
    for (int i = t; i < 16 * 40; i += 256) w2s[i] = __ldg(&W2[i]);
    if (t < OUT_CH) b2s[t] = __ldg(&b2[t]);
    __syncthreads();

    int node = blockIdx.x * 256 + t;
    if (node >= N_NODES) return;

    float g[16];
    const float4* gp = (const float4*)(g_g2 + (size_t)node * 8);
    float4 v0 = gp[0], v1 = gp[1], v2 = gp[2], v3 = gp[3];
    g[0] = v0.x; g[1] = v0.y; g[2] = v0.z;  g[3] = v0.w;
    g[4] = v1.x; g[5] = v1.y; g[6] = v1.z;  g[7] = v1.w;
    g[8] = v2.x; g[9] = v2.y; g[10] = v2.z; g[11] = v2.w;
    g[12] = v3.x; g[13] = v3.y; g[14] = v3.z; g[15] = v3.w;

    float lg[40];
#pragma unroll
    for (int o = 0; o < 40; o++) lg[o] = b2s[o];
#pragma unroll
    for (int k = 0; k < 16; k++) {
        float gk = g[k];
#pragma unroll
        for (int o4 = 0; o4 < 10; o4++) {
            float4 w = *(const float4*)&w2s[k * 40 + o4 * 4];
            lg[o4 * 4 + 0] = fmaf(gk, w.x, lg[o4 * 4 + 0]);
            lg[o4 * 4 + 1] = fmaf(gk, w.y, lg[o4 * 4 + 1]);
            lg[o4 * 4 + 2] = fmaf(gk, w.z, lg[o4 * 4 + 2]);
            lg[o4 * 4 + 3] = fmaf(gk, w.w, lg[o4 * 4 + 3]);
        }
    }

    float m = lg[0];
#pragma unroll
    for (int o = 1; o < 40; o++) m = fmaxf(m, lg[o]);
    float s = 0.f;
#pragma unroll
    for (int o = 0; o < 40; o++) s += __expf(lg[o] - m);
    float lse = m + __logf(s);

    float4* op = (float4*)(out + (size_t)node * 40);
#pragma unroll
    for (int o4 = 0; o4 < 10; o4++)
        op[o4] = make_float4(lg[o4 * 4 + 0] - lse, lg[o4 * 4 + 1] - lse,
                             lg[o4 * 4 + 2] - lse, lg[o4 * 4 + 3] - lse);
}

// ---------------------------------------------------------------
extern "C" void kernel_launch(void* const* d_in, const int* in_sizes, int n_in,
                              void* d_out, int out_size) {
    const float* x  = (const float*)d_in[0];
    const void*  ei = d_in[1];
    const float* W1 = (const float*)d_in[2];
    const float* b1 = (const float*)d_in[3];
    const float* W2 = (const float*)d_in[4];
    const float* b2 = (const float*)d_in[5];
    float* out = (float*)d_out;

    static void* cntp = nullptr;
    if (!cntp) cudaGetSymbolAddress(&cntp, g_cnt);

    cudaMemsetAsync(cntp, 0, N_NODES * sizeof(int), 0);
    k_build <<<(N_EDGES / 4 + 255) / 256, 256>>>(ei);
    k_gemm1 <<<(N_NODES + 255) / 256, 256>>>(x, W1);
    k_agg0  <<<(N_NODES * 8 + 511) / 512, 512>>>(b1);
    k_agg1  <<<(N_NODES * 32 + 255) / 256, 256>>>();
    k_gemm2 <<<(N_NODES + 255) / 256, 256>>>(W2, b2, out);
}